// round 1
// baseline (speedup 1.0000x reference)
#include <cuda_runtime.h>
#include <math.h>

// Problem constants
#define DM     512
#define NSEQ   2048
#define CH     8
#define BATCH  4
#define BCN    (BATCH*CH)            // 32 attention batches
#define MROWS  (BATCH*NSEQ*CH)       // 65536 projection rows
#define OUT_OFF_ATTN ((size_t)BATCH*NSEQ*CH*DM)   // 33554432: attn starts after out

// Scratch (device globals — allocation-free per harness rules)
__device__ float g_qp[(size_t)BCN*NSEQ*DM];   // [b,c,n,d]
__device__ float g_kp[(size_t)BCN*NSEQ*DM];
__device__ float g_vp[(size_t)BCN*NSEQ*DM];
__device__ float g_ctx[(size_t)BCN*NSEQ*DM];  // [b,c,n,d]

#define BM 128
#define BN 128
#define BK 16

// ---------------------------------------------------------------------------
// Projection GEMM: out[r, :] = A[m, :] @ W + bias, with row remap m->r.
// MODE 0: qkv proj. input rows (b,n,c) -> dest rows (b,c,n). no relu.
// MODE 1: out proj. input rows (b,c,n) -> dest rows (b,n,c). relu.
// A: [65536, 512] row-major contiguous. W: [512, 512] row-major ([in,out]).
// ---------------------------------------------------------------------------
template<int MODE>
__global__ __launch_bounds__(256) void proj_kernel(
    const float* __restrict__ A, const float* __restrict__ W,
    const float* __restrict__ bias, float* __restrict__ out)
{
    __shared__ float As[BK][BM + 1];   // pad: conflict-free transpose stores
    __shared__ float Bs[BK][BN];

    const int tid = threadIdx.x;
    const int tx = tid & 15;
    const int ty = tid >> 4;
    const int rowBase = blockIdx.y * BM;
    const int colBase = blockIdx.x * BN;

    const int a_r = tid >> 2;            // 0..63
    const int a_c = (tid & 3) << 2;      // 0,4,8,12
    const int b_k = tid >> 5;            // 0..7
    const int b_n = (tid & 31) << 2;     // 0..124

    float acc[8][8];
    #pragma unroll
    for (int i = 0; i < 8; i++)
        #pragma unroll
        for (int j = 0; j < 8; j++) acc[i][j] = 0.f;

    for (int kb = 0; kb < DM; kb += BK) {
        #pragma unroll
        for (int s = 0; s < 2; s++) {
            int r = a_r + s * 64;
            float4 va = *reinterpret_cast<const float4*>(
                &A[(size_t)(rowBase + r) * DM + kb + a_c]);
            As[a_c + 0][r] = va.x;
            As[a_c + 1][r] = va.y;
            As[a_c + 2][r] = va.z;
            As[a_c + 3][r] = va.w;
        }
        #pragma unroll
        for (int s = 0; s < 2; s++) {
            int k = b_k + s * 8;
            *reinterpret_cast<float4*>(&Bs[k][b_n]) =
                *reinterpret_cast<const float4*>(&W[(size_t)(kb + k) * DM + colBase + b_n]);
        }
        __syncthreads();
        #pragma unroll
        for (int k = 0; k < BK; k++) {
            float a[8], b[8];
            #pragma unroll
            for (int i = 0; i < 8; i++) a[i] = As[k][ty * 8 + i];
            float4 b0 = *reinterpret_cast<const float4*>(&Bs[k][tx * 8]);
            float4 b1 = *reinterpret_cast<const float4*>(&Bs[k][tx * 8 + 4]);
            b[0]=b0.x; b[1]=b0.y; b[2]=b0.z; b[3]=b0.w;
            b[4]=b1.x; b[5]=b1.y; b[6]=b1.z; b[7]=b1.w;
            #pragma unroll
            for (int i = 0; i < 8; i++)
                #pragma unroll
                for (int j = 0; j < 8; j++)
                    acc[i][j] += a[i] * b[j];
        }
        __syncthreads();
    }

    float bb[8];
    #pragma unroll
    for (int j = 0; j < 8; j++) bb[j] = bias[colBase + tx * 8 + j];

    #pragma unroll
    for (int i = 0; i < 8; i++) {
        int m = rowBase + ty * 8 + i;
        int r;
        if (MODE == 0) {                       // (b,n,c) -> (b,c,n)
            int bb_ = m >> 14, n = (m >> 3) & 2047, c = m & 7;
            r = (bb_ << 14) + (c << 11) + n;
        } else {                               // (b,c,n) -> (b,n,c)
            int bb_ = m >> 14, c = (m >> 11) & 7, n = m & 2047;
            r = (bb_ << 14) + (n << 3) + c;
        }
        float4 v0, v1;
        v0.x = acc[i][0] + bb[0]; v0.y = acc[i][1] + bb[1];
        v0.z = acc[i][2] + bb[2]; v0.w = acc[i][3] + bb[3];
        v1.x = acc[i][4] + bb[4]; v1.y = acc[i][5] + bb[5];
        v1.z = acc[i][6] + bb[6]; v1.w = acc[i][7] + bb[7];
        if (MODE == 1) {
            v0.x = fmaxf(v0.x, 0.f); v0.y = fmaxf(v0.y, 0.f);
            v0.z = fmaxf(v0.z, 0.f); v0.w = fmaxf(v0.w, 0.f);
            v1.x = fmaxf(v1.x, 0.f); v1.y = fmaxf(v1.y, 0.f);
            v1.z = fmaxf(v1.z, 0.f); v1.w = fmaxf(v1.w, 0.f);
        }
        float* o = &out[(size_t)r * DM + colBase + tx * 8];
        *reinterpret_cast<float4*>(o)     = v0;
        *reinterpret_cast<float4*>(o + 4) = v1;
    }
}

// ---------------------------------------------------------------------------
// Scores: per z in [0,32): S[n,m] = scale * dot(Q[z,n,:], K[z,m,:])
// NT GEMM: both operands K-major -> both tiles transposed on load.
// ---------------------------------------------------------------------------
__global__ __launch_bounds__(256) void scores_kernel(
    const float* __restrict__ Qg, const float* __restrict__ Kg,
    float* __restrict__ S)
{
    const int z = blockIdx.z;
    const float* Aq = Qg + (size_t)z * NSEQ * DM;
    const float* Bk = Kg + (size_t)z * NSEQ * DM;
    float* Sp = S + (size_t)z * NSEQ * NSEQ;

    __shared__ float As[BK][BM + 1];
    __shared__ float Bs[BK][BN + 1];

    const int tid = threadIdx.x;
    const int tx = tid & 15;
    const int ty = tid >> 4;
    const int rowBase = blockIdx.y * BM;   // n
    const int colBase = blockIdx.x * BN;   // m

    const int a_r = tid >> 2;
    const int a_c = (tid & 3) << 2;

    float acc[8][8];
    #pragma unroll
    for (int i = 0; i < 8; i++)
        #pragma unroll
        for (int j = 0; j < 8; j++) acc[i][j] = 0.f;

    for (int kb = 0; kb < DM; kb += BK) {
        #pragma unroll
        for (int s = 0; s < 2; s++) {
            int r = a_r + s * 64;
            float4 va = *reinterpret_cast<const float4*>(
                &Aq[(size_t)(rowBase + r) * DM + kb + a_c]);
            As[a_c + 0][r] = va.x; As[a_c + 1][r] = va.y;
            As[a_c + 2][r] = va.z; As[a_c + 3][r] = va.w;
            float4 vb = *reinterpret_cast<const float4*>(
                &Bk[(size_t)(colBase + r) * DM + kb + a_c]);
            Bs[a_c + 0][r] = vb.x; Bs[a_c + 1][r] = vb.y;
            Bs[a_c + 2][r] = vb.z; Bs[a_c + 3][r] = vb.w;
        }
        __syncthreads();
        #pragma unroll
        for (int k = 0; k < BK; k++) {
            float a[8], b[8];
            #pragma unroll
            for (int i = 0; i < 8; i++) a[i] = As[k][ty * 8 + i];
            #pragma unroll
            for (int j = 0; j < 8; j++) b[j] = Bs[k][tx * 8 + j];
            #pragma unroll
            for (int i = 0; i < 8; i++)
                #pragma unroll
                for (int j = 0; j < 8; j++)
                    acc[i][j] += a[i] * b[j];
        }
        __syncthreads();
    }

    const float scale = 0.04419417382415922f;   // 1/sqrt(512)
    #pragma unroll
    for (int i = 0; i < 8; i++) {
        int n = rowBase + ty * 8 + i;
        float4 v0, v1;
        v0.x = acc[i][0]*scale; v0.y = acc[i][1]*scale;
        v0.z = acc[i][2]*scale; v0.w = acc[i][3]*scale;
        v1.x = acc[i][4]*scale; v1.y = acc[i][5]*scale;
        v1.z = acc[i][6]*scale; v1.w = acc[i][7]*scale;
        float* o = &Sp[(size_t)n * NSEQ + colBase + tx * 8];
        *reinterpret_cast<float4*>(o)     = v0;
        *reinterpret_cast<float4*>(o + 4) = v1;
    }
}

// ---------------------------------------------------------------------------
// Row softmax over 2048 elements, in place. One block per row.
// ---------------------------------------------------------------------------
__global__ __launch_bounds__(256) void softmax_kernel(float* __restrict__ S)
{
    float* p = S + (size_t)blockIdx.x * NSEQ;
    const int t = threadIdx.x;
    __shared__ float red[8];

    float v[8];
    #pragma unroll
    for (int i = 0; i < 8; i++) v[i] = p[t + i * 256];

    float mx = v[0];
    #pragma unroll
    for (int i = 1; i < 8; i++) mx = fmaxf(mx, v[i]);
    #pragma unroll
    for (int o = 16; o > 0; o >>= 1) mx = fmaxf(mx, __shfl_xor_sync(0xffffffffu, mx, o));
    if ((t & 31) == 0) red[t >> 5] = mx;
    __syncthreads();
    mx = red[0];
    #pragma unroll
    for (int i = 1; i < 8; i++) mx = fmaxf(mx, red[i]);
    __syncthreads();

    float e[8], s = 0.f;
    #pragma unroll
    for (int i = 0; i < 8; i++) { e[i] = expf(v[i] - mx); s += e[i]; }
    #pragma unroll
    for (int o = 16; o > 0; o >>= 1) s += __shfl_xor_sync(0xffffffffu, s, o);
    if ((t & 31) == 0) red[t >> 5] = s;
    __syncthreads();
    s = red[0];
    #pragma unroll
    for (int i = 1; i < 8; i++) s += red[i];
    float inv = 1.f / s;
    #pragma unroll
    for (int i = 0; i < 8; i++) p[t + i * 256] = e[i] * inv;
}

// ---------------------------------------------------------------------------
// AV: per z: ctx[n,d] = attn[n,:] @ V[:,d].  NN GEMM, K=2048.
// ---------------------------------------------------------------------------
__global__ __launch_bounds__(256) void av_kernel(
    const float* __restrict__ attn, const float* __restrict__ Vg,
    float* __restrict__ ctx)
{
    const int z = blockIdx.z;
    const float* Ap = attn + (size_t)z * NSEQ * NSEQ;
    const float* Bp = Vg   + (size_t)z * NSEQ * DM;
    float* Cp       = ctx  + (size_t)z * NSEQ * DM;

    __shared__ float As[BK][BM + 1];
    __shared__ float Bs[BK][BN];

    const int tid = threadIdx.x;
    const int tx = tid & 15;
    const int ty = tid >> 4;
    const int rowBase = blockIdx.y * BM;   // n
    const int colBase = blockIdx.x * BN;   // d

    const int a_r = tid >> 2;
    const int a_c = (tid & 3) << 2;
    const int b_k = tid >> 5;
    const int b_n = (tid & 31) << 2;

    float acc[8][8];
    #pragma unroll
    for (int i = 0; i < 8; i++)
        #pragma unroll
        for (int j = 0; j < 8; j++) acc[i][j] = 0.f;

    for (int kb = 0; kb < NSEQ; kb += BK) {
        #pragma unroll
        for (int s = 0; s < 2; s++) {
            int r = a_r + s * 64;
            float4 va = *reinterpret_cast<const float4*>(
                &Ap[(size_t)(rowBase + r) * NSEQ + kb + a_c]);
            As[a_c + 0][r] = va.x; As[a_c + 1][r] = va.y;
            As[a_c + 2][r] = va.z; As[a_c + 3][r] = va.w;
        }
        #pragma unroll
        for (int s = 0; s < 2; s++) {
            int k = b_k + s * 8;
            *reinterpret_cast<float4*>(&Bs[k][b_n]) =
                *reinterpret_cast<const float4*>(&Bp[(size_t)(kb + k) * DM + colBase + b_n]);
        }
        __syncthreads();
        #pragma unroll
        for (int k = 0; k < BK; k++) {
            float a[8], b[8];
            #pragma unroll
            for (int i = 0; i < 8; i++) a[i] = As[k][ty * 8 + i];
            float4 b0 = *reinterpret_cast<const float4*>(&Bs[k][tx * 8]);
            float4 b1 = *reinterpret_cast<const float4*>(&Bs[k][tx * 8 + 4]);
            b[0]=b0.x; b[1]=b0.y; b[2]=b0.z; b[3]=b0.w;
            b[4]=b1.x; b[5]=b1.y; b[6]=b1.z; b[7]=b1.w;
            #pragma unroll
            for (int i = 0; i < 8; i++)
                #pragma unroll
                for (int j = 0; j < 8; j++)
                    acc[i][j] += a[i] * b[j];
        }
        __syncthreads();
    }

    #pragma unroll
    for (int i = 0; i < 8; i++) {
        int n = rowBase + ty * 8 + i;
        float4 v0, v1;
        v0.x = acc[i][0]; v0.y = acc[i][1]; v0.z = acc[i][2]; v0.w = acc[i][3];
        v1.x = acc[i][4]; v1.y = acc[i][5]; v1.z = acc[i][6]; v1.w = acc[i][7];
        float* o = &Cp[(size_t)n * DM + colBase + tx * 8];
        *reinterpret_cast<float4*>(o)     = v0;
        *reinterpret_cast<float4*>(o + 4) = v1;
    }
}

// ---------------------------------------------------------------------------
extern "C" void kernel_launch(void* const* d_in, const int* in_sizes, int n_in,
                              void* d_out, int out_size)
{
    const float* q  = (const float*)d_in[0];
    const float* k  = (const float*)d_in[1];
    const float* v  = (const float*)d_in[2];
    const float* Wq = (const float*)d_in[3];
    const float* bq = (const float*)d_in[4];
    const float* Wk = (const float*)d_in[5];
    const float* bk = (const float*)d_in[6];
    const float* Wv = (const float*)d_in[7];
    const float* bv = (const float*)d_in[8];
    const float* Wo = (const float*)d_in[9];
    const float* bo = (const float*)d_in[10];

    float* out  = (float*)d_out;               // [b,n,c,d]
    float* attn = out + OUT_OFF_ATTN;          // [b,c,n,m]

    void *pq, *pk, *pv, *pc;
    cudaGetSymbolAddress(&pq, g_qp);
    cudaGetSymbolAddress(&pk, g_kp);
    cudaGetSymbolAddress(&pv, g_vp);
    cudaGetSymbolAddress(&pc, g_ctx);
    float* qp  = (float*)pq;
    float* kp  = (float*)pk;
    float* vp  = (float*)pv;
    float* ctx = (float*)pc;

    dim3 gProj(DM / BN, MROWS / BM);                 // (4, 512)
    proj_kernel<0><<<gProj, 256>>>(q, Wq, bq, qp);
    proj_kernel<0><<<gProj, 256>>>(k, Wk, bk, kp);
    proj_kernel<0><<<gProj, 256>>>(v, Wv, bv, vp);

    dim3 gS(NSEQ / BN, NSEQ / BM, BCN);              // (16, 16, 32)
    scores_kernel<<<gS, 256>>>(qp, kp, attn);

    softmax_kernel<<<BCN * NSEQ, 256>>>(attn);       // 65536 rows

    dim3 gAV(DM / BN, NSEQ / BM, BCN);               // (4, 16, 32)
    av_kernel<<<gAV, 256>>>(attn, vp, ctx);

    proj_kernel<1><<<gProj, 256>>>(ctx, Wo, bo, out);
}

// round 3
// speedup vs baseline: 3.5927x; 3.5927x over previous
#include <cuda_runtime.h>
#include <cuda_fp16.h>
#include <mma.h>
#include <math.h>

using namespace nvcuda;

// Problem constants
#define DM     512
#define NSEQ   2048
#define CH     8
#define BATCH  4
#define BCN    (BATCH*CH)            // 32 attention batches
#define MROWS  (BATCH*NSEQ*CH)       // 65536 projection rows
#define OUT_OFF_ATTN ((size_t)BATCH*NSEQ*CH*DM)   // attn starts after out

// Half-precision scratch (device globals — allocation-free per harness rules)
__device__ __half g_qp[(size_t)BCN*NSEQ*DM];   // [b,c,n,d]
__device__ __half g_kp[(size_t)BCN*NSEQ*DM];
__device__ __half g_vp[(size_t)BCN*NSEQ*DM];
__device__ __half g_ctx[(size_t)BCN*NSEQ*DM];  // [b,c,n,d]

#define BM 128
#define BN 128
#define BK 32
#define LDA 40     // half stride for 128x32 tiles (conflict-free ldmatrix)
#define LDB 136    // half stride for 32x128 tiles
#define LDS_SC 20  // float stride for epilogue scratch

__device__ __forceinline__ uint2 f4_to_h4(float4 v) {
    __half2 lo = __floats2half2_rn(v.x, v.y);
    __half2 hi = __floats2half2_rn(v.z, v.w);
    uint2 r;
    r.x = *reinterpret_cast<unsigned*>(&lo);
    r.y = *reinterpret_cast<unsigned*>(&hi);
    return r;
}

// ---------------------------------------------------------------------------
// proj_in: out[r,:] = half( A[m,:] @ W + b ), A fp32, rows (b,n,c)->(b,c,n)
// ---------------------------------------------------------------------------
__global__ __launch_bounds__(256) void proj_in_kernel(
    const float* __restrict__ A, const float* __restrict__ W,
    const float* __restrict__ bias, __half* __restrict__ out)
{
    __shared__ __half As[BM][LDA];
    __shared__ __half Bs[BK][LDB];
    __shared__ float sc[8][16][LDS_SC];

    const int tid = threadIdx.x;
    const int wid = tid >> 5, lane = tid & 31;
    const int wr = wid >> 1, wc = wid & 1;
    const int rowBase = blockIdx.y * BM, colBase = blockIdx.x * BN;

    wmma::fragment<wmma::accumulator, 16, 16, 16, float> acc[2][4];
    #pragma unroll
    for (int i = 0; i < 2; i++)
        #pragma unroll
        for (int j = 0; j < 4; j++) wmma::fill_fragment(acc[i][j], 0.f);

    const int ar = tid >> 1, ac = (tid & 1) << 4;   // A: 128 rows, 16 floats each half-row
    const int br = tid >> 3, bc = (tid & 7) << 4;   // W: 32 rows, 16 floats per thread

    for (int kb = 0; kb < DM; kb += BK) {
        #pragma unroll
        for (int i = 0; i < 4; i++) {
            float4 v = *reinterpret_cast<const float4*>(
                &A[(size_t)(rowBase + ar) * DM + kb + ac + i * 4]);
            *reinterpret_cast<uint2*>(&As[ar][ac + i * 4]) = f4_to_h4(v);
        }
        #pragma unroll
        for (int i = 0; i < 4; i++) {
            float4 v = *reinterpret_cast<const float4*>(
                &W[(size_t)(kb + br) * DM + colBase + bc + i * 4]);
            *reinterpret_cast<uint2*>(&Bs[br][bc + i * 4]) = f4_to_h4(v);
        }
        __syncthreads();
        #pragma unroll
        for (int ks = 0; ks < BK; ks += 16) {
            wmma::fragment<wmma::matrix_a, 16, 16, 16, __half, wmma::row_major> af[2];
            wmma::fragment<wmma::matrix_b, 16, 16, 16, __half, wmma::row_major> bf[4];
            #pragma unroll
            for (int i = 0; i < 2; i++)
                wmma::load_matrix_sync(af[i], &As[wr * 32 + i * 16][ks], LDA);
            #pragma unroll
            for (int j = 0; j < 4; j++)
                wmma::load_matrix_sync(bf[j], &Bs[ks][wc * 64 + j * 16], LDB);
            #pragma unroll
            for (int i = 0; i < 2; i++)
                #pragma unroll
                for (int j = 0; j < 4; j++)
                    wmma::mma_sync(acc[i][j], af[i], bf[j], acc[i][j]);
        }
        __syncthreads();
    }

    const int er = lane >> 1, ec = (lane & 1) << 3;
    #pragma unroll
    for (int i = 0; i < 2; i++)
        #pragma unroll
        for (int j = 0; j < 4; j++) {
            wmma::store_matrix_sync(&sc[wid][0][0], acc[i][j], LDS_SC, wmma::mem_row_major);
            __syncwarp();
            int gr = rowBase + wr * 32 + i * 16 + er;
            int gc = colBase + wc * 64 + j * 16 + ec;
            int b = gr >> 14, n = (gr >> 3) & 2047, c = gr & 7;
            int rr = (b << 14) + (c << 11) + n;
            __half h[8];
            #pragma unroll
            for (int t = 0; t < 8; t++)
                h[t] = __float2half_rn(sc[wid][er][ec + t] + bias[gc + t]);
            *reinterpret_cast<uint4*>(&out[(size_t)rr * DM + gc]) =
                *reinterpret_cast<uint4*>(h);
            __syncwarp();
        }
}

// ---------------------------------------------------------------------------
// proj_out: out[r,:] = relu( A[m,:] @ W + b ), A half, rows (b,c,n)->(b,n,c)
// ---------------------------------------------------------------------------
__global__ __launch_bounds__(256) void proj_out_kernel(
    const __half* __restrict__ A, const float* __restrict__ W,
    const float* __restrict__ bias, float* __restrict__ out)
{
    __shared__ __half As[BM][LDA];
    __shared__ __half Bs[BK][LDB];
    __shared__ float sc[8][16][LDS_SC];

    const int tid = threadIdx.x;
    const int wid = tid >> 5, lane = tid & 31;
    const int wr = wid >> 1, wc = wid & 1;
    const int rowBase = blockIdx.y * BM, colBase = blockIdx.x * BN;

    wmma::fragment<wmma::accumulator, 16, 16, 16, float> acc[2][4];
    #pragma unroll
    for (int i = 0; i < 2; i++)
        #pragma unroll
        for (int j = 0; j < 4; j++) wmma::fill_fragment(acc[i][j], 0.f);

    const int ar = tid >> 1, ach = (tid & 1) << 4;  // A: half tile, 16 halves per thread
    const int br = tid >> 3, bc = (tid & 7) << 4;

    for (int kb = 0; kb < DM; kb += BK) {
        #pragma unroll
        for (int i = 0; i < 2; i++) {
            *reinterpret_cast<uint4*>(&As[ar][ach + i * 8]) =
                *reinterpret_cast<const uint4*>(
                    &A[(size_t)(rowBase + ar) * DM + kb + ach + i * 8]);
        }
        #pragma unroll
        for (int i = 0; i < 4; i++) {
            float4 v = *reinterpret_cast<const float4*>(
                &W[(size_t)(kb + br) * DM + colBase + bc + i * 4]);
            *reinterpret_cast<uint2*>(&Bs[br][bc + i * 4]) = f4_to_h4(v);
        }
        __syncthreads();
        #pragma unroll
        for (int ks = 0; ks < BK; ks += 16) {
            wmma::fragment<wmma::matrix_a, 16, 16, 16, __half, wmma::row_major> af[2];
            wmma::fragment<wmma::matrix_b, 16, 16, 16, __half, wmma::row_major> bf[4];
            #pragma unroll
            for (int i = 0; i < 2; i++)
                wmma::load_matrix_sync(af[i], &As[wr * 32 + i * 16][ks], LDA);
            #pragma unroll
            for (int j = 0; j < 4; j++)
                wmma::load_matrix_sync(bf[j], &Bs[ks][wc * 64 + j * 16], LDB);
            #pragma unroll
            for (int i = 0; i < 2; i++)
                #pragma unroll
                for (int j = 0; j < 4; j++)
                    wmma::mma_sync(acc[i][j], af[i], bf[j], acc[i][j]);
        }
        __syncthreads();
    }

    const int er = lane >> 1, ec = (lane & 1) << 3;
    #pragma unroll
    for (int i = 0; i < 2; i++)
        #pragma unroll
        for (int j = 0; j < 4; j++) {
            wmma::store_matrix_sync(&sc[wid][0][0], acc[i][j], LDS_SC, wmma::mem_row_major);
            __syncwarp();
            int gr = rowBase + wr * 32 + i * 16 + er;
            int gc = colBase + wc * 64 + j * 16 + ec;
            int b = gr >> 14, c = (gr >> 11) & 7, n = gr & 2047;
            int rr = (b << 14) + (n << 3) + c;
            float o[8];
            #pragma unroll
            for (int t = 0; t < 8; t++)
                o[t] = fmaxf(sc[wid][er][ec + t] + bias[gc + t], 0.f);
            float* op = &out[(size_t)rr * DM + gc];
            *reinterpret_cast<float4*>(op)     = *reinterpret_cast<float4*>(&o[0]);
            *reinterpret_cast<float4*>(op + 4) = *reinterpret_cast<float4*>(&o[4]);
            __syncwarp();
        }
}

// ---------------------------------------------------------------------------
// scores: per z: S[n,m] = scale * dot(Q[z,n,:], K[z,m,:]).  NT, half in, f32 out
// ---------------------------------------------------------------------------
__global__ __launch_bounds__(256) void scores_kernel(
    const __half* __restrict__ Qg, const __half* __restrict__ Kg,
    float* __restrict__ S)
{
    const int z = blockIdx.z;
    const __half* Aq = Qg + (size_t)z * NSEQ * DM;
    const __half* Bk = Kg + (size_t)z * NSEQ * DM;
    float* Sp = S + (size_t)z * NSEQ * NSEQ;

    __shared__ __half As[BM][LDA];
    __shared__ __half BsT[BM][LDA];   // [m][k]
    __shared__ float sc[8][16][LDS_SC];

    const int tid = threadIdx.x;
    const int wid = tid >> 5, lane = tid & 31;
    const int wr = wid >> 1, wc = wid & 1;
    const int rowBase = blockIdx.y * BM, colBase = blockIdx.x * BN;

    wmma::fragment<wmma::accumulator, 16, 16, 16, float> acc[2][4];
    #pragma unroll
    for (int i = 0; i < 2; i++)
        #pragma unroll
        for (int j = 0; j < 4; j++) wmma::fill_fragment(acc[i][j], 0.f);

    const int ar = tid >> 1, ach = (tid & 1) << 4;

    for (int kb = 0; kb < DM; kb += BK) {
        #pragma unroll
        for (int i = 0; i < 2; i++) {
            *reinterpret_cast<uint4*>(&As[ar][ach + i * 8]) =
                *reinterpret_cast<const uint4*>(
                    &Aq[(size_t)(rowBase + ar) * DM + kb + ach + i * 8]);
            *reinterpret_cast<uint4*>(&BsT[ar][ach + i * 8]) =
                *reinterpret_cast<const uint4*>(
                    &Bk[(size_t)(colBase + ar) * DM + kb + ach + i * 8]);
        }
        __syncthreads();
        #pragma unroll
        for (int ks = 0; ks < BK; ks += 16) {
            wmma::fragment<wmma::matrix_a, 16, 16, 16, __half, wmma::row_major> af[2];
            wmma::fragment<wmma::matrix_b, 16, 16, 16, __half, wmma::col_major> bf[4];
            #pragma unroll
            for (int i = 0; i < 2; i++)
                wmma::load_matrix_sync(af[i], &As[wr * 32 + i * 16][ks], LDA);
            #pragma unroll
            for (int j = 0; j < 4; j++)
                wmma::load_matrix_sync(bf[j], &BsT[wc * 64 + j * 16][ks], LDA);
            #pragma unroll
            for (int i = 0; i < 2; i++)
                #pragma unroll
                for (int j = 0; j < 4; j++)
                    wmma::mma_sync(acc[i][j], af[i], bf[j], acc[i][j]);
        }
        __syncthreads();
    }

    const float scale = 0.04419417382415922f;  // 1/sqrt(512)
    const int er = lane >> 1, ec = (lane & 1) << 3;
    #pragma unroll
    for (int i = 0; i < 2; i++)
        #pragma unroll
        for (int j = 0; j < 4; j++) {
            wmma::store_matrix_sync(&sc[wid][0][0], acc[i][j], LDS_SC, wmma::mem_row_major);
            __syncwarp();
            int gn = rowBase + wr * 32 + i * 16 + er;
            int gm = colBase + wc * 64 + j * 16 + ec;
            float o[8];
            #pragma unroll
            for (int t = 0; t < 8; t++) o[t] = sc[wid][er][ec + t] * scale;
            float* op = &Sp[(size_t)gn * NSEQ + gm];
            *reinterpret_cast<float4*>(op)     = *reinterpret_cast<float4*>(&o[0]);
            *reinterpret_cast<float4*>(op + 4) = *reinterpret_cast<float4*>(&o[4]);
            __syncwarp();
        }
}

// ---------------------------------------------------------------------------
// Row softmax over 2048 elements, in place (fp32, exact)
// ---------------------------------------------------------------------------
__global__ __launch_bounds__(256) void softmax_kernel(float* __restrict__ S)
{
    float* p = S + (size_t)blockIdx.x * NSEQ;
    const int t = threadIdx.x;
    __shared__ float red[8];

    float v[8];
    #pragma unroll
    for (int i = 0; i < 8; i++) v[i] = p[t + i * 256];

    float mx = v[0];
    #pragma unroll
    for (int i = 1; i < 8; i++) mx = fmaxf(mx, v[i]);
    #pragma unroll
    for (int o = 16; o > 0; o >>= 1) mx = fmaxf(mx, __shfl_xor_sync(0xffffffffu, mx, o));
    if ((t & 31) == 0) red[t >> 5] = mx;
    __syncthreads();
    mx = red[0];
    #pragma unroll
    for (int i = 1; i < 8; i++) mx = fmaxf(mx, red[i]);
    __syncthreads();

    float e[8], s = 0.f;
    #pragma unroll
    for (int i = 0; i < 8; i++) { e[i] = expf(v[i] - mx); s += e[i]; }
    #pragma unroll
    for (int o = 16; o > 0; o >>= 1) s += __shfl_xor_sync(0xffffffffu, s, o);
    if ((t & 31) == 0) red[t >> 5] = s;
    __syncthreads();
    s = red[0];
    #pragma unroll
    for (int i = 1; i < 8; i++) s += red[i];
    float inv = 1.f / s;
    #pragma unroll
    for (int i = 0; i < 8; i++) p[t + i * 256] = e[i] * inv;
}

// ---------------------------------------------------------------------------
// AV: per z: ctx[n,d] = attn[n,:] @ V[:,d].  attn fp32 (cvt), V half, out half
// ---------------------------------------------------------------------------
__global__ __launch_bounds__(256) void av_kernel(
    const float* __restrict__ attn, const __half* __restrict__ Vg,
    __half* __restrict__ ctx)
{
    const int z = blockIdx.z;
    const float* Ap = attn + (size_t)z * NSEQ * NSEQ;
    const __half* Bp = Vg + (size_t)z * NSEQ * DM;
    __half* Cp = ctx + (size_t)z * NSEQ * DM;

    __shared__ __half As[BM][LDA];
    __shared__ __half Bs[BK][LDB];
    __shared__ float sc[8][16][LDS_SC];

    const int tid = threadIdx.x;
    const int wid = tid >> 5, lane = tid & 31;
    const int wr = wid >> 1, wc = wid & 1;
    const int rowBase = blockIdx.y * BM, colBase = blockIdx.x * BN;

    wmma::fragment<wmma::accumulator, 16, 16, 16, float> acc[2][4];
    #pragma unroll
    for (int i = 0; i < 2; i++)
        #pragma unroll
        for (int j = 0; j < 4; j++) wmma::fill_fragment(acc[i][j], 0.f);

    const int ar = tid >> 1, ac = (tid & 1) << 4;   // attn fp32 tile
    const int br = tid >> 3;                         // V half tile: 32 rows

    for (int kb = 0; kb < NSEQ; kb += BK) {
        #pragma unroll
        for (int i = 0; i < 4; i++) {
            float4 v = *reinterpret_cast<const float4*>(
                &Ap[(size_t)(rowBase + ar) * NSEQ + kb + ac + i * 4]);
            *reinterpret_cast<uint2*>(&As[ar][ac + i * 4]) = f4_to_h4(v);
        }
        #pragma unroll
        for (int i = 0; i < 2; i++) {
            int col = ((tid & 7) * 2 + i) * 8;
            *reinterpret_cast<uint4*>(&Bs[br][col]) =
                *reinterpret_cast<const uint4*>(
                    &Bp[(size_t)(kb + br) * DM + colBase + col]);
        }
        __syncthreads();
        #pragma unroll
        for (int ks = 0; ks < BK; ks += 16) {
            wmma::fragment<wmma::matrix_a, 16, 16, 16, __half, wmma::row_major> af[2];
            wmma::fragment<wmma::matrix_b, 16, 16, 16, __half, wmma::row_major> bf[4];
            #pragma unroll
            for (int i = 0; i < 2; i++)
                wmma::load_matrix_sync(af[i], &As[wr * 32 + i * 16][ks], LDA);
            #pragma unroll
            for (int j = 0; j < 4; j++)
                wmma::load_matrix_sync(bf[j], &Bs[ks][wc * 64 + j * 16], LDB);
            #pragma unroll
            for (int i = 0; i < 2; i++)
                #pragma unroll
                for (int j = 0; j < 4; j++)
                    wmma::mma_sync(acc[i][j], af[i], bf[j], acc[i][j]);
        }
        __syncthreads();
    }

    const int er = lane >> 1, ec = (lane & 1) << 3;
    #pragma unroll
    for (int i = 0; i < 2; i++)
        #pragma unroll
        for (int j = 0; j < 4; j++) {
            wmma::store_matrix_sync(&sc[wid][0][0], acc[i][j], LDS_SC, wmma::mem_row_major);
            __syncwarp();
            int gn = rowBase + wr * 32 + i * 16 + er;
            int gd = colBase + wc * 64 + j * 16 + ec;
            __half h[8];
            #pragma unroll
            for (int t = 0; t < 8; t++) h[t] = __float2half_rn(sc[wid][er][ec + t]);
            *reinterpret_cast<uint4*>(&Cp[(size_t)gn * DM + gd]) =
                *reinterpret_cast<uint4*>(h);
            __syncwarp();
        }
}

// ---------------------------------------------------------------------------
extern "C" void kernel_launch(void* const* d_in, const int* in_sizes, int n_in,
                              void* d_out, int out_size)
{
    const float* q  = (const float*)d_in[0];
    const float* k  = (const float*)d_in[1];
    const float* v  = (const float*)d_in[2];
    const float* Wq = (const float*)d_in[3];
    const float* bq = (const float*)d_in[4];
    const float* Wk = (const float*)d_in[5];
    const float* bk = (const float*)d_in[6];
    const float* Wv = (const float*)d_in[7];
    const float* bv = (const float*)d_in[8];
    const float* Wo = (const float*)d_in[9];
    const float* bo = (const float*)d_in[10];

    float* out  = (float*)d_out;               // [b,n,c,d]
    float* attn = out + OUT_OFF_ATTN;          // [b,c,n,m]

    void *pq, *pk, *pv, *pc;
    cudaGetSymbolAddress(&pq, g_qp);
    cudaGetSymbolAddress(&pk, g_kp);
    cudaGetSymbolAddress(&pv, g_vp);
    cudaGetSymbolAddress(&pc, g_ctx);
    __half* qp  = (__half*)pq;
    __half* kp  = (__half*)pk;
    __half* vp  = (__half*)pv;
    __half* ctx = (__half*)pc;

    dim3 gProj(DM / BN, MROWS / BM);                 // (4, 512)
    proj_in_kernel<<<gProj, 256>>>(q, Wq, bq, qp);
    proj_in_kernel<<<gProj, 256>>>(k, Wk, bk, kp);
    proj_in_kernel<<<gProj, 256>>>(v, Wv, bv, vp);

    dim3 gS(NSEQ / BN, NSEQ / BM, BCN);              // (16, 16, 32)
    scores_kernel<<<gS, 256>>>(qp, kp, attn);

    softmax_kernel<<<BCN * NSEQ, 256>>>(attn);       // 65536 rows

    dim3 gAV(DM / BN, NSEQ / BM, BCN);               // (4, 16, 32)
    av_kernel<<<gAV, 256>>>(attn, vp, ctx);

    proj_out_kernel<<<gProj, 256>>>(ctx, Wo, bo, out);
}

// round 5
// speedup vs baseline: 4.5407x; 1.2639x over previous
#include <cuda_runtime.h>
#include <cuda_fp16.h>
#include <cstdint>
#include <math.h>

// ---------------------------------------------------------------------------
#define DM     512
#define NSEQ   2048
#define CH     8
#define BATCH  4
#define BCN    (BATCH*CH)            // 32 attention batches
#define MROWS  (BATCH*NSEQ*CH)       // 65536 projection rows
#define OUT_OFF_ATTN ((size_t)BATCH*NSEQ*CH*DM)

// Scratch (device globals — allocation-free per harness rules)
__device__ __half g_qp [(size_t)BCN*NSEQ*DM];    // [z][n][d]
__device__ __half g_kp [(size_t)BCN*NSEQ*DM];    // [z][m][d]
__device__ __half g_vp [(size_t)BCN*NSEQ*DM];    // [z][m][d]
__device__ __half g_ctx[(size_t)BCN*NSEQ*DM];    // [z][n][d]
__device__ __half g_wt [4*(size_t)DM*DM];        // W^T as [out][in], fp16

// ---------------------------------------------------------------------------
__device__ __forceinline__ uint32_t smem_u32(const void* p) {
    uint32_t a;
    asm("{ .reg .u64 t; cvta.to.shared.u64 t, %1; cvt.u32.u64 %0, t; }"
        : "=r"(a) : "l"(p));
    return a;
}
__device__ __forceinline__ void cpa16(uint32_t d, const void* s) {
    asm volatile("cp.async.cg.shared.global [%0], [%1], 16;" :: "r"(d), "l"(s));
}
__device__ __forceinline__ void cpcommit() {
    asm volatile("cp.async.commit_group;" ::: "memory");
}
template<int N> __device__ __forceinline__ void cpwait() {
    asm volatile("cp.async.wait_group %0;" :: "n"(N) : "memory");
}
#define LDSM4(r, a)                                                           \
    asm volatile("ldmatrix.sync.aligned.m8n8.x4.shared.b16 {%0,%1,%2,%3}, [%4];" \
        : "=r"((r)[0]), "=r"((r)[1]), "=r"((r)[2]), "=r"((r)[3]) : "r"(a))
#define LDSM4T(r, a)                                                          \
    asm volatile("ldmatrix.sync.aligned.m8n8.x4.trans.shared.b16 {%0,%1,%2,%3}, [%4];" \
        : "=r"((r)[0]), "=r"((r)[1]), "=r"((r)[2]), "=r"((r)[3]) : "r"(a))

__device__ __forceinline__ void mma16816(float* c, const uint32_t* a,
                                         uint32_t b0, uint32_t b1) {
    asm volatile(
        "mma.sync.aligned.m16n8k16.row.col.f32.f16.f16.f32 "
        "{%0,%1,%2,%3}, {%4,%5,%6,%7}, {%8,%9}, {%0,%1,%2,%3};"
        : "+f"(c[0]), "+f"(c[1]), "+f"(c[2]), "+f"(c[3])
        : "r"(a[0]), "r"(a[1]), "r"(a[2]), "r"(a[3]), "r"(b0), "r"(b1));
}

// ---------------------------------------------------------------------------
// One GEMM kernel, block tile 128x256x32, 8 warps of 64x64.
// MODE 0: projection  C = A(f32)@W^T + b,  row remap (b,n,c)->(b,c,n), half out
// MODE 2: scores      C = scale * Q @ K^T, half in, f32 out
// MODE 3: AV          C = attn(f32->h) @ V, V loaded [m][d] w/ ldmatrix.trans
// MODE 4: out proj    C = relu(ctx(h)@Wo^T + b), remap (b,c,n)->(b,n,c), f32
// ---------------------------------------------------------------------------
#define ABUF (128*40)

template<int MODE>
__global__ __launch_bounds__(256) void gemm_mma(
    const void* __restrict__ Ag, const __half* __restrict__ Bg,
    const float* __restrict__ bias, void* __restrict__ Cg)
{
    extern __shared__ __half sh[];
    constexpr int  K     = (MODE == 3) ? NSEQ : DM;
    constexpr int  ITERS = K / 32;
    constexpr bool ACVT  = (MODE == 0) || (MODE == 3);
    constexpr bool BTR   = (MODE == 3);
    constexpr int  LDAE  = (MODE == 3) ? NSEQ : DM;
    constexpr int  BBUF  = BTR ? (32*264) : (256*40);

    __half* As = sh;
    __half* Bs = sh + 2*ABUF;

    const int tid = threadIdx.x, lane = tid & 31, wid = tid >> 5;
    const int wr = wid >> 2, wc = wid & 3;
    const int z = blockIdx.z;
    const int rowBase = blockIdx.y * 128, colBase = blockIdx.x * 256;

    const float*  Af = (MODE == 3) ? (const float*)Ag + (size_t)z*NSEQ*NSEQ
                                   : (const float*)Ag;
    const __half* Ah = (MODE == 2) ? (const __half*)Ag + (size_t)z*NSEQ*DM
                                   : (const __half*)Ag;
    const __half* Bp = Bg + ((MODE == 2 || MODE == 3) ? (size_t)z*NSEQ*DM : 0);

    const uint32_t sA = smem_u32(As);
    const uint32_t sB = smem_u32(Bs);

    float acc[4][8][4];
    #pragma unroll
    for (int i = 0; i < 4; i++)
        #pragma unroll
        for (int j = 0; j < 8; j++)
            #pragma unroll
            for (int q = 0; q < 4; q++) acc[i][j][q] = 0.f;

    // ---- loaders ----
    const int avr = tid & 127;      // CVT: row
    const int avh = tid >> 7;       // CVT: 16-col chunk (0/1)
    float4 fA[4];

    auto loadA_cvt = [&](int kb) {
        const float* s = Af + (size_t)(rowBase + avr) * LDAE + kb + avh * 16;
        fA[0] = *(const float4*)s;       fA[1] = *(const float4*)(s + 4);
        fA[2] = *(const float4*)(s + 8); fA[3] = *(const float4*)(s + 12);
    };
    auto stsA_cvt = [&](int buf) {
        __half hv[16];
        #pragma unroll
        for (int u = 0; u < 4; u++) {
            hv[u*4+0] = __float2half_rn(fA[u].x);
            hv[u*4+1] = __float2half_rn(fA[u].y);
            hv[u*4+2] = __float2half_rn(fA[u].z);
            hv[u*4+3] = __float2half_rn(fA[u].w);
        }
        __half* d = As + buf*ABUF + avr*40 + avh*16;
        *(uint4*)d       = *(uint4*)hv;
        *((uint4*)d + 1) = *(uint4*)(hv + 8);
    };
    auto issueA_async = [&](int buf, int kb) {
        #pragma unroll
        for (int i = 0; i < 2; i++) {
            int idx = tid + i*256;
            int h = idx & 3, r = idx >> 2;
            cpa16(sA + (uint32_t)(buf*ABUF + r*40 + h*8)*2,
                  Ah + (size_t)(rowBase + r)*LDAE + kb + h*8);
        }
    };
    auto issueB = [&](int buf, int kb) {
        if constexpr (BTR) {
            #pragma unroll
            for (int i = 0; i < 4; i++) {
                int idx = tid + i*256;
                int r = idx >> 5, h = idx & 31;
                cpa16(sB + (uint32_t)(buf*BBUF + r*264 + h*8)*2,
                      Bp + (size_t)(kb + r)*DM + colBase + h*8);
            }
        } else {
            #pragma unroll
            for (int i = 0; i < 4; i++) {
                int idx = tid + i*256;
                int h = idx & 3, r = idx >> 2;
                cpa16(sB + (uint32_t)(buf*BBUF + r*40 + h*8)*2,
                      Bp + (size_t)(colBase + r)*DM + kb + h*8);
            }
        }
    };

    // ---- prologue ----
    if constexpr (ACVT) { loadA_cvt(0); stsA_cvt(0); }
    else issueA_async(0, 0);
    issueB(0, 0);
    cpcommit();

    // ---- main loop ----
    for (int it = 0; it < ITERS; ++it) {
        const int cur = it & 1;
        if (it + 1 < ITERS) {
            const int nb = (it + 1) & 1, kb = (it + 1) * 32;
            if constexpr (ACVT) loadA_cvt(kb);   // regs in flight over compute
            else issueA_async(nb, kb);
            issueB(nb, kb);
            cpcommit();
            cpwait<1>();
        } else {
            cpwait<0>();
        }
        __syncthreads();

        #pragma unroll
        for (int ks = 0; ks < 2; ks++) {
            uint32_t a[4][4], b[4][4];
            #pragma unroll
            for (int i = 0; i < 4; i++) {
                int row = wr*64 + i*16 + (lane & 15);
                int col = ks*16 + ((lane >> 4) << 3);
                LDSM4(a[i], sA + (uint32_t)(cur*ABUF + row*40 + col)*2);
            }
            #pragma unroll
            for (int t = 0; t < 4; t++) {
                if constexpr (BTR) {
                    int row = ks*16 + (lane & 7) + (((lane >> 3) & 1) << 3);
                    int col = wc*64 + t*16 + ((lane >> 4) << 3);
                    LDSM4T(b[t], sB + (uint32_t)(cur*BBUF + row*264 + col)*2);
                } else {
                    int row = wc*64 + t*16 + (lane & 7) + ((lane >> 4) << 3);
                    int col = ks*16 + (((lane >> 3) & 1) << 3);
                    LDSM4(b[t], sB + (uint32_t)(cur*BBUF + row*40 + col)*2);
                }
            }
            #pragma unroll
            for (int i = 0; i < 4; i++)
                #pragma unroll
                for (int t = 0; t < 4; t++) {
                    mma16816(acc[i][2*t],   a[i], b[t][0], b[t][1]);
                    mma16816(acc[i][2*t+1], a[i], b[t][2], b[t][3]);
                }
        }
        if (it + 1 < ITERS) {
            if constexpr (ACVT) stsA_cvt((it + 1) & 1);
        }
        __syncthreads();
    }

    // ---- epilogue: direct from mma accumulators ----
    const int g = lane >> 2, tig = lane & 3;
    float bb0[8], bb1[8];
    if constexpr (MODE == 0 || MODE == 4) {
        #pragma unroll
        for (int j = 0; j < 8; j++) {
            int gc = colBase + wc*64 + j*8 + tig*2;
            bb0[j] = __ldg(&bias[gc]);
            bb1[j] = __ldg(&bias[gc + 1]);
        }
    }
    const float scale = 0.04419417382415922f;   // 1/sqrt(512)

    #pragma unroll
    for (int i = 0; i < 4; i++) {
        int r0 = rowBase + wr*64 + i*16 + g;
        #pragma unroll
        for (int rr = 0; rr < 2; rr++) {
            int gr = r0 + rr*8;
            #pragma unroll
            for (int j = 0; j < 8; j++) {
                float c0 = acc[i][j][rr*2 + 0], c1 = acc[i][j][rr*2 + 1];
                int gc = colBase + wc*64 + j*8 + tig*2;
                if constexpr (MODE == 0) {
                    int b = gr >> 14, n = (gr >> 3) & 2047, ch = gr & 7;
                    int zz = (b << 3) | ch;
                    *(__half2*)((__half*)Cg + ((size_t)zz*NSEQ + n)*DM + gc) =
                        __floats2half2_rn(c0 + bb0[j], c1 + bb1[j]);
                } else if constexpr (MODE == 2) {
                    float2 o; o.x = c0 * scale; o.y = c1 * scale;
                    *(float2*)((float*)Cg + ((size_t)z*NSEQ + gr)*NSEQ + gc) = o;
                } else if constexpr (MODE == 3) {
                    *(__half2*)((__half*)Cg + ((size_t)z*NSEQ + gr)*DM + gc) =
                        __floats2half2_rn(c0, c1);
                } else {  // MODE 4
                    int b = gr >> 14, ch = (gr >> 11) & 7, n = gr & 2047;
                    int rm = (b << 14) | (n << 3) | ch;
                    float2 o;
                    o.x = fmaxf(c0 + bb0[j], 0.f);
                    o.y = fmaxf(c1 + bb1[j], 0.f);
                    *(float2*)((float*)Cg + (size_t)rm*DM + gc) = o;
                }
            }
        }
    }
}

// ---------------------------------------------------------------------------
// W transpose + fp16 convert: W[in][out] f32 -> Wt[out][in] half
// ---------------------------------------------------------------------------
__global__ __launch_bounds__(256) void prep_w_kernel(
    const float* __restrict__ W, __half* __restrict__ Wt)
{
    __shared__ float t[32][33];
    const int bx = blockIdx.x * 32;   // out
    const int by = blockIdx.y * 32;   // in
    const int tx = threadIdx.x & 31;
    const int ty = threadIdx.x >> 5;  // 0..7
    #pragma unroll
    for (int i = 0; i < 4; i++) {
        int r = ty * 4 + i;
        t[r][tx] = W[(size_t)(by + r) * DM + bx + tx];
    }
    __syncthreads();
    #pragma unroll
    for (int i = 0; i < 4; i++) {
        int r = ty * 4 + i;   // out-local
        Wt[(size_t)(bx + r) * DM + by + tx] = __float2half_rn(t[tx][r]);
    }
}

// ---------------------------------------------------------------------------
// Row softmax over 2048 elements, in place (fp32, exact)
// ---------------------------------------------------------------------------
__global__ __launch_bounds__(256) void softmax_kernel(float* __restrict__ S)
{
    float* p = S + (size_t)blockIdx.x * NSEQ;
    const int t = threadIdx.x;
    __shared__ float red[8];

    float v[8];
    #pragma unroll
    for (int i = 0; i < 8; i++) v[i] = p[t + i * 256];

    float mx = v[0];
    #pragma unroll
    for (int i = 1; i < 8; i++) mx = fmaxf(mx, v[i]);
    #pragma unroll
    for (int o = 16; o > 0; o >>= 1) mx = fmaxf(mx, __shfl_xor_sync(0xffffffffu, mx, o));
    if ((t & 31) == 0) red[t >> 5] = mx;
    __syncthreads();
    mx = red[0];
    #pragma unroll
    for (int i = 1; i < 8; i++) mx = fmaxf(mx, red[i]);
    __syncthreads();

    float e[8], s = 0.f;
    #pragma unroll
    for (int i = 0; i < 8; i++) { e[i] = expf(v[i] - mx); s += e[i]; }
    #pragma unroll
    for (int o = 16; o > 0; o >>= 1) s += __shfl_xor_sync(0xffffffffu, s, o);
    if ((t & 31) == 0) red[t >> 5] = s;
    __syncthreads();
    s = red[0];
    #pragma unroll
    for (int i = 1; i < 8; i++) s += red[i];
    float inv = 1.f / s;
    #pragma unroll
    for (int i = 0; i < 8; i++) p[t + i * 256] = e[i] * inv;
}

// ---------------------------------------------------------------------------
#define SMEM_BYTES ((2*ABUF + 2*256*40) * 2)   // 61440

extern "C" void kernel_launch(void* const* d_in, const int* in_sizes, int n_in,
                              void* d_out, int out_size)
{
    const float* q  = (const float*)d_in[0];
    const float* k  = (const float*)d_in[1];
    const float* v  = (const float*)d_in[2];
    const float* Wq = (const float*)d_in[3];
    const float* bq = (const float*)d_in[4];
    const float* Wk = (const float*)d_in[5];
    const float* bk = (const float*)d_in[6];
    const float* Wv = (const float*)d_in[7];
    const float* bv = (const float*)d_in[8];
    const float* Wo = (const float*)d_in[9];
    const float* bo = (const float*)d_in[10];

    float* out  = (float*)d_out;               // [b,n,c,d]
    float* attn = out + OUT_OFF_ATTN;          // [b,c,n,m]

    void *pq, *pk, *pv, *pc, *pw;
    cudaGetSymbolAddress(&pq, g_qp);
    cudaGetSymbolAddress(&pk, g_kp);
    cudaGetSymbolAddress(&pv, g_vp);
    cudaGetSymbolAddress(&pc, g_ctx);
    cudaGetSymbolAddress(&pw, g_wt);
    __half* qp  = (__half*)pq;
    __half* kp  = (__half*)pk;
    __half* vp  = (__half*)pv;
    __half* ctx = (__half*)pc;
    __half* wt  = (__half*)pw;

    cudaFuncSetAttribute(gemm_mma<0>, cudaFuncAttributeMaxDynamicSharedMemorySize, SMEM_BYTES);
    cudaFuncSetAttribute(gemm_mma<2>, cudaFuncAttributeMaxDynamicSharedMemorySize, SMEM_BYTES);
    cudaFuncSetAttribute(gemm_mma<3>, cudaFuncAttributeMaxDynamicSharedMemorySize, SMEM_BYTES);
    cudaFuncSetAttribute(gemm_mma<4>, cudaFuncAttributeMaxDynamicSharedMemorySize, SMEM_BYTES);

    // transpose + convert weights
    dim3 gW(16, 16);
    prep_w_kernel<<<gW, 256>>>(Wq, wt + 0 * (size_t)DM * DM);
    prep_w_kernel<<<gW, 256>>>(Wk, wt + 1 * (size_t)DM * DM);
    prep_w_kernel<<<gW, 256>>>(Wv, wt + 2 * (size_t)DM * DM);
    prep_w_kernel<<<gW, 256>>>(Wo, wt + 3 * (size_t)DM * DM);

    // projections: M=65536, N=512
    dim3 gP(DM / 256, MROWS / 128, 1);           // (2, 512)
    gemm_mma<0><<<gP, 256, SMEM_BYTES>>>(q, wt + 0 * (size_t)DM * DM, bq, qp);
    gemm_mma<0><<<gP, 256, SMEM_BYTES>>>(k, wt + 1 * (size_t)DM * DM, bk, kp);
    gemm_mma<0><<<gP, 256, SMEM_BYTES>>>(v, wt + 2 * (size_t)DM * DM, bv, vp);

    // scores: per z, M=N=2048, K=512
    dim3 gS(NSEQ / 256, NSEQ / 128, BCN);        // (8, 16, 32)
    gemm_mma<2><<<gS, 256, SMEM_BYTES>>>(qp, kp, nullptr, attn);

    softmax_kernel<<<BCN * NSEQ, 256>>>(attn);   // 65536 rows

    // AV: per z, M=2048, N=512, K=2048
    dim3 gA(DM / 256, NSEQ / 128, BCN);          // (2, 16, 32)
    gemm_mma<3><<<gA, 256, SMEM_BYTES>>>(attn, vp, nullptr, ctx);

    // out projection
    gemm_mma<4><<<gP, 256, SMEM_BYTES>>>(ctx, wt + 3 * (size_t)DM * DM, bo, out);
}

// round 6
// speedup vs baseline: 5.6328x; 1.2405x over previous
#include <cuda_runtime.h>
#include <cuda_fp16.h>
#include <cstdint>
#include <math.h>

// ---------------------------------------------------------------------------
#define DM     512
#define NSEQ   2048
#define CH     8
#define BATCH  4
#define BCN    (BATCH*CH)            // 32 attention batches
#define MROWS  (BATCH*NSEQ*CH)       // 65536 projection rows
#define OUT_OFF_ATTN ((size_t)BATCH*NSEQ*CH*DM)

// Scratch (device globals — allocation-free per harness rules)
__device__ __half g_qp [(size_t)BCN*NSEQ*DM];     // [z][n][d]
__device__ __half g_kp [(size_t)BCN*NSEQ*DM];     // [z][m][d]
__device__ __half g_vp [(size_t)BCN*NSEQ*DM];     // [z][m][d]
__device__ __half g_ctx[(size_t)BCN*NSEQ*DM];     // [z][n][d]
__device__ __half g_sc [(size_t)BCN*NSEQ*NSEQ];   // fp16 scores / normalized attn
__device__ __half g_wt [4*(size_t)DM*DM];         // W^T as [out][in], fp16

// ---------------------------------------------------------------------------
__device__ __forceinline__ uint32_t smem_u32(const void* p) {
    uint32_t a;
    asm("{ .reg .u64 t; cvta.to.shared.u64 t, %1; cvt.u32.u64 %0, t; }"
        : "=r"(a) : "l"(p));
    return a;
}
__device__ __forceinline__ void cpa16(uint32_t d, const void* s) {
    asm volatile("cp.async.cg.shared.global [%0], [%1], 16;" :: "r"(d), "l"(s));
}
__device__ __forceinline__ void cpcommit() {
    asm volatile("cp.async.commit_group;" ::: "memory");
}
template<int N> __device__ __forceinline__ void cpwait() {
    asm volatile("cp.async.wait_group %0;" :: "n"(N) : "memory");
}
#define LDSM4(r, a)                                                           \
    asm volatile("ldmatrix.sync.aligned.m8n8.x4.shared.b16 {%0,%1,%2,%3}, [%4];" \
        : "=r"((r)[0]), "=r"((r)[1]), "=r"((r)[2]), "=r"((r)[3]) : "r"(a))
#define LDSM4T(r, a)                                                          \
    asm volatile("ldmatrix.sync.aligned.m8n8.x4.trans.shared.b16 {%0,%1,%2,%3}, [%4];" \
        : "=r"((r)[0]), "=r"((r)[1]), "=r"((r)[2]), "=r"((r)[3]) : "r"(a))

__device__ __forceinline__ void mma16816(float* c, const uint32_t* a,
                                         uint32_t b0, uint32_t b1) {
    asm volatile(
        "mma.sync.aligned.m16n8k16.row.col.f32.f16.f16.f32 "
        "{%0,%1,%2,%3}, {%4,%5,%6,%7}, {%8,%9}, {%0,%1,%2,%3};"
        : "+f"(c[0]), "+f"(c[1]), "+f"(c[2]), "+f"(c[3])
        : "r"(a[0]), "r"(a[1]), "r"(a[2]), "r"(a[3]), "r"(b0), "r"(b1));
}

// ---------------------------------------------------------------------------
// Block tile 128x256xKC(=64), 8 warps of 64x64.
// MODE 0: projection  C = A(f32)@W^T + b,  remap (b,n,c)->(b,c,n), half out
// MODE 2: scores      C = scale * Q @ K^T, half in, HALF out (to g_sc)
// MODE 3: AV          C = attnH @ V, A half, V loaded [m][d] w/ ldmatrix.trans
// MODE 4: out proj    C = relu(ctx(h)@Wo^T + b), remap (b,c,n)->(b,n,c), f32
// ---------------------------------------------------------------------------
#define KC    64
#define LDA_S 72           // halves: 64 + 8 pad
#define LDB_T 264          // halves for BTR tiles (256 + 8 pad)
#define ABUF  (128*LDA_S)
#define BBUF  (256*LDA_S)  // >= 64*LDB_T (16896)

template<int MODE>
__global__ __launch_bounds__(256) void gemm_mma(
    const void* __restrict__ Ag, const __half* __restrict__ Bg,
    const float* __restrict__ bias, void* __restrict__ Cg)
{
    extern __shared__ __half sh[];
    constexpr int  K     = (MODE == 3) ? NSEQ : DM;
    constexpr int  ITERS = K / KC;
    constexpr bool ACVT  = (MODE == 0);
    constexpr bool BTR   = (MODE == 3);
    constexpr int  LDAE  = (MODE == 3) ? NSEQ : DM;

    __half* As = sh;
    __half* Bs = sh + 2*ABUF;

    const int tid = threadIdx.x, lane = tid & 31, wid = tid >> 5;
    const int wr = wid >> 2, wc = wid & 3;
    const int z = blockIdx.z;
    const int rowBase = blockIdx.y * 128, colBase = blockIdx.x * 256;

    const float*  Af = (const float*)Ag;
    const __half* Ah = (const __half*)Ag +
        (MODE == 2 ? (size_t)z*NSEQ*DM : MODE == 3 ? (size_t)z*NSEQ*NSEQ : 0);
    const __half* Bp = Bg + ((MODE == 2 || MODE == 3) ? (size_t)z*NSEQ*DM : 0);

    const uint32_t sA = smem_u32(As);
    const uint32_t sB = smem_u32(Bs);

    float acc[4][8][4];
    #pragma unroll
    for (int i = 0; i < 4; i++)
        #pragma unroll
        for (int j = 0; j < 8; j++)
            #pragma unroll
            for (int q = 0; q < 4; q++) acc[i][j][q] = 0.f;

    // ---- loaders ----
    const int avr = tid & 127;      // CVT: row
    const int avh = tid >> 7;       // CVT: 32-col half (0/1)
    float4 fA[8];

    auto loadA_cvt = [&](int kb) {
        const float* s = Af + (size_t)(rowBase + avr) * LDAE + kb + avh * 32;
        #pragma unroll
        for (int u = 0; u < 8; u++) fA[u] = *(const float4*)(s + u*4);
    };
    auto stsA_cvt = [&](int buf) {
        __half hv[32];
        #pragma unroll
        for (int u = 0; u < 8; u++) {
            hv[u*4+0] = __float2half_rn(fA[u].x);
            hv[u*4+1] = __float2half_rn(fA[u].y);
            hv[u*4+2] = __float2half_rn(fA[u].z);
            hv[u*4+3] = __float2half_rn(fA[u].w);
        }
        __half* d = As + buf*ABUF + avr*LDA_S + avh*32;
        #pragma unroll
        for (int u = 0; u < 4; u++)
            *((uint4*)d + u) = ((uint4*)hv)[u];
    };
    auto issueA_async = [&](int buf, int kb) {
        #pragma unroll
        for (int i = 0; i < 4; i++) {
            int idx = tid + i*256;
            int h = idx & 7, r = idx >> 3;
            cpa16(sA + (uint32_t)(buf*ABUF + r*LDA_S + h*8)*2,
                  Ah + (size_t)(rowBase + r)*LDAE + kb + h*8);
        }
    };
    auto issueB = [&](int buf, int kb) {
        if constexpr (BTR) {
            #pragma unroll
            for (int i = 0; i < 8; i++) {
                int idx = tid + i*256;
                int r = idx >> 5, h = idx & 31;
                cpa16(sB + (uint32_t)(buf*BBUF + r*LDB_T + h*8)*2,
                      Bp + (size_t)(kb + r)*DM + colBase + h*8);
            }
        } else {
            #pragma unroll
            for (int i = 0; i < 8; i++) {
                int idx = tid + i*256;
                int h = idx & 7, r = idx >> 3;
                cpa16(sB + (uint32_t)(buf*BBUF + r*LDA_S + h*8)*2,
                      Bp + (size_t)(colBase + r)*DM + kb + h*8);
            }
        }
    };

    // ---- prologue ----
    if constexpr (ACVT) { loadA_cvt(0); stsA_cvt(0); }
    else issueA_async(0, 0);
    issueB(0, 0);
    cpcommit();

    // ---- main loop ----
    for (int it = 0; it < ITERS; ++it) {
        const int cur = it & 1;
        if (it + 1 < ITERS) {
            const int nb = (it + 1) & 1, kb = (it + 1) * KC;
            if constexpr (ACVT) loadA_cvt(kb);
            else issueA_async(nb, kb);
            issueB(nb, kb);
            cpcommit();
            cpwait<1>();
        } else {
            cpwait<0>();
        }
        __syncthreads();

        #pragma unroll
        for (int ks = 0; ks < KC/16; ks++) {
            uint32_t a[4][4], b[4][4];
            #pragma unroll
            for (int i = 0; i < 4; i++) {
                int row = wr*64 + i*16 + (lane & 15);
                int col = ks*16 + ((lane >> 4) << 3);
                LDSM4(a[i], sA + (uint32_t)(cur*ABUF + row*LDA_S + col)*2);
            }
            #pragma unroll
            for (int t = 0; t < 4; t++) {
                if constexpr (BTR) {
                    int row = ks*16 + (lane & 7) + (((lane >> 3) & 1) << 3);
                    int col = wc*64 + t*16 + ((lane >> 4) << 3);
                    LDSM4T(b[t], sB + (uint32_t)(cur*BBUF + row*LDB_T + col)*2);
                } else {
                    int row = wc*64 + t*16 + (lane & 7) + ((lane >> 4) << 3);
                    int col = ks*16 + (((lane >> 3) & 1) << 3);
                    LDSM4(b[t], sB + (uint32_t)(cur*BBUF + row*LDA_S + col)*2);
                }
            }
            #pragma unroll
            for (int i = 0; i < 4; i++)
                #pragma unroll
                for (int t = 0; t < 4; t++) {
                    mma16816(acc[i][2*t],   a[i], b[t][0], b[t][1]);
                    mma16816(acc[i][2*t+1], a[i], b[t][2], b[t][3]);
                }
        }
        if (it + 1 < ITERS) {
            if constexpr (ACVT) stsA_cvt((it + 1) & 1);
        }
        __syncthreads();
    }

    // ---- epilogue: direct from mma accumulators ----
    const int g = lane >> 2, tig = lane & 3;
    float bb0[8], bb1[8];
    if constexpr (MODE == 0 || MODE == 4) {
        #pragma unroll
        for (int j = 0; j < 8; j++) {
            int gc = colBase + wc*64 + j*8 + tig*2;
            bb0[j] = __ldg(&bias[gc]);
            bb1[j] = __ldg(&bias[gc + 1]);
        }
    }
    const float scale = 0.04419417382415922f;   // 1/sqrt(512)

    #pragma unroll
    for (int i = 0; i < 4; i++) {
        int r0 = rowBase + wr*64 + i*16 + g;
        #pragma unroll
        for (int rr = 0; rr < 2; rr++) {
            int gr = r0 + rr*8;
            #pragma unroll
            for (int j = 0; j < 8; j++) {
                float c0 = acc[i][j][rr*2 + 0], c1 = acc[i][j][rr*2 + 1];
                int gc = colBase + wc*64 + j*8 + tig*2;
                if constexpr (MODE == 0) {
                    int b = gr >> 14, n = (gr >> 3) & 2047, ch = gr & 7;
                    int zz = (b << 3) | ch;
                    *(__half2*)((__half*)Cg + ((size_t)zz*NSEQ + n)*DM + gc) =
                        __floats2half2_rn(c0 + bb0[j], c1 + bb1[j]);
                } else if constexpr (MODE == 2) {
                    *(__half2*)((__half*)Cg + ((size_t)z*NSEQ + gr)*NSEQ + gc) =
                        __floats2half2_rn(c0 * scale, c1 * scale);
                } else if constexpr (MODE == 3) {
                    *(__half2*)((__half*)Cg + ((size_t)z*NSEQ + gr)*DM + gc) =
                        __floats2half2_rn(c0, c1);
                } else {  // MODE 4
                    int b = gr >> 14, ch = (gr >> 11) & 7, n = gr & 2047;
                    int rm = (b << 14) | (n << 3) | ch;
                    float2 o;
                    o.x = fmaxf(c0 + bb0[j], 0.f);
                    o.y = fmaxf(c1 + bb1[j], 0.f);
                    *(float2*)((float*)Cg + (size_t)rm*DM + gc) = o;
                }
            }
        }
    }
}

// ---------------------------------------------------------------------------
// W transpose + fp16 convert: W[in][out] f32 -> Wt[out][in] half
// ---------------------------------------------------------------------------
__global__ __launch_bounds__(256) void prep_w_kernel(
    const float* __restrict__ W, __half* __restrict__ Wt)
{
    __shared__ float t[32][33];
    const int bx = blockIdx.x * 32;   // out
    const int by = blockIdx.y * 32;   // in
    const int tx = threadIdx.x & 31;
    const int ty = threadIdx.x >> 5;  // 0..7
    #pragma unroll
    for (int i = 0; i < 4; i++) {
        int r = ty * 4 + i;
        t[r][tx] = W[(size_t)(by + r) * DM + bx + tx];
    }
    __syncthreads();
    #pragma unroll
    for (int i = 0; i < 4; i++) {
        int r = ty * 4 + i;   // out-local
        Wt[(size_t)(bx + r) * DM + by + tx] = __float2half_rn(t[tx][r]);
    }
}

// ---------------------------------------------------------------------------
// Softmax: warp per row. Reads fp16 scores from Sh, writes fp32 attn to Af
// and normalized fp16 back to Sh (in place) for the AV GEMM.
// ---------------------------------------------------------------------------
__global__ __launch_bounds__(256) void softmax_kernel(
    __half* __restrict__ Sh, float* __restrict__ Af)
{
    const int row  = blockIdx.x * 8 + (threadIdx.x >> 5);
    const int lane = threadIdx.x & 31;
    __half* p = Sh + (size_t)row * NSEQ;
    float*  o = Af + (size_t)row * NSEQ;

    // 64 halves per lane: 16 x uint2 (4 halves), coalesced per 128-col stripe
    uint2 hv[16];
    #pragma unroll
    for (int j = 0; j < 16; j++)
        hv[j] = *(const uint2*)(p + lane*4 + j*128);

    float v[64];
    #pragma unroll
    for (int j = 0; j < 16; j++) {
        float2 a = __half22float2(*(__half2*)&hv[j].x);
        float2 b = __half22float2(*(__half2*)&hv[j].y);
        v[4*j+0] = a.x; v[4*j+1] = a.y; v[4*j+2] = b.x; v[4*j+3] = b.y;
    }

    float mx = v[0];
    #pragma unroll
    for (int i = 1; i < 64; i++) mx = fmaxf(mx, v[i]);
    #pragma unroll
    for (int s = 16; s > 0; s >>= 1)
        mx = fmaxf(mx, __shfl_xor_sync(0xffffffffu, mx, s));

    float sum = 0.f;
    #pragma unroll
    for (int i = 0; i < 64; i++) { v[i] = expf(v[i] - mx); sum += v[i]; }
    #pragma unroll
    for (int s = 16; s > 0; s >>= 1)
        sum += __shfl_xor_sync(0xffffffffu, sum, s);
    const float inv = 1.f / sum;

    #pragma unroll
    for (int j = 0; j < 16; j++) {
        float4 f;
        f.x = v[4*j+0] * inv; f.y = v[4*j+1] * inv;
        f.z = v[4*j+2] * inv; f.w = v[4*j+3] * inv;
        *(float4*)(o + lane*4 + j*128) = f;
        __half2 h0 = __floats2half2_rn(f.x, f.y);
        __half2 h1 = __floats2half2_rn(f.z, f.w);
        uint2 u; u.x = *(uint32_t*)&h0; u.y = *(uint32_t*)&h1;
        *(uint2*)(p + lane*4 + j*128) = u;
    }
}

// ---------------------------------------------------------------------------
#define SMEM_BYTES ((2*ABUF + 2*BBUF) * 2)   // 110592

extern "C" void kernel_launch(void* const* d_in, const int* in_sizes, int n_in,
                              void* d_out, int out_size)
{
    const float* q  = (const float*)d_in[0];
    const float* k  = (const float*)d_in[1];
    const float* v  = (const float*)d_in[2];
    const float* Wq = (const float*)d_in[3];
    const float* bq = (const float*)d_in[4];
    const float* Wk = (const float*)d_in[5];
    const float* bk = (const float*)d_in[6];
    const float* Wv = (const float*)d_in[7];
    const float* bv = (const float*)d_in[8];
    const float* Wo = (const float*)d_in[9];
    const float* bo = (const float*)d_in[10];

    float* out  = (float*)d_out;               // [b,n,c,d]
    float* attn = out + OUT_OFF_ATTN;          // [b,c,n,m]

    void *pq, *pk, *pv, *pc, *ps, *pw;
    cudaGetSymbolAddress(&pq, g_qp);
    cudaGetSymbolAddress(&pk, g_kp);
    cudaGetSymbolAddress(&pv, g_vp);
    cudaGetSymbolAddress(&pc, g_ctx);
    cudaGetSymbolAddress(&ps, g_sc);
    cudaGetSymbolAddress(&pw, g_wt);
    __half* qp  = (__half*)pq;
    __half* kp  = (__half*)pk;
    __half* vp  = (__half*)pv;
    __half* ctx = (__half*)pc;
    __half* sc  = (__half*)ps;
    __half* wt  = (__half*)pw;

    cudaFuncSetAttribute(gemm_mma<0>, cudaFuncAttributeMaxDynamicSharedMemorySize, SMEM_BYTES);
    cudaFuncSetAttribute(gemm_mma<2>, cudaFuncAttributeMaxDynamicSharedMemorySize, SMEM_BYTES);
    cudaFuncSetAttribute(gemm_mma<3>, cudaFuncAttributeMaxDynamicSharedMemorySize, SMEM_BYTES);
    cudaFuncSetAttribute(gemm_mma<4>, cudaFuncAttributeMaxDynamicSharedMemorySize, SMEM_BYTES);

    // transpose + convert weights
    dim3 gW(16, 16);
    prep_w_kernel<<<gW, 256>>>(Wq, wt + 0 * (size_t)DM * DM);
    prep_w_kernel<<<gW, 256>>>(Wk, wt + 1 * (size_t)DM * DM);
    prep_w_kernel<<<gW, 256>>>(Wv, wt + 2 * (size_t)DM * DM);
    prep_w_kernel<<<gW, 256>>>(Wo, wt + 3 * (size_t)DM * DM);

    // projections: M=65536, N=512
    dim3 gP(DM / 256, MROWS / 128, 1);           // (2, 512)
    gemm_mma<0><<<gP, 256, SMEM_BYTES>>>(q, wt + 0 * (size_t)DM * DM, bq, qp);
    gemm_mma<0><<<gP, 256, SMEM_BYTES>>>(k, wt + 1 * (size_t)DM * DM, bk, kp);
    gemm_mma<0><<<gP, 256, SMEM_BYTES>>>(v, wt + 2 * (size_t)DM * DM, bv, vp);

    // scores: per z, M=N=2048, K=512, fp16 out to g_sc
    dim3 gS(NSEQ / 256, NSEQ / 128, BCN);        // (8, 16, 32)
    gemm_mma<2><<<gS, 256, SMEM_BYTES>>>(qp, kp, nullptr, sc);

    // softmax: fp16 in -> fp32 attn + fp16 normalized (in place)
    softmax_kernel<<<BCN * NSEQ / 8, 256>>>(sc, attn);

    // AV: per z, M=2048, N=512, K=2048, A = fp16 normalized attn
    dim3 gA(DM / 256, NSEQ / 128, BCN);          // (2, 16, 32)
    gemm_mma<3><<<gA, 256, SMEM_BYTES>>>(sc, vp, nullptr, ctx);

    // out projection
    gemm_mma<4><<<gP, 256, SMEM_BYTES>>>(ctx, wt + 3 * (size_t)DM * DM, bo, out);
}

// round 7
// speedup vs baseline: 5.6515x; 1.0033x over previous
#include <cuda_runtime.h>
#include <cuda_fp16.h>
#include <cstdint>
#include <math.h>

// ---------------------------------------------------------------------------
#define DM     512
#define NSEQ   2048
#define CH     8
#define BATCH  4
#define BCN    (BATCH*CH)            // 32 attention batches
#define MROWS  (BATCH*NSEQ*CH)       // 65536 projection rows
#define OUT_OFF_ATTN ((size_t)BATCH*NSEQ*CH*DM)

// Scratch (device globals — allocation-free per harness rules)
__device__ __half g_qp [(size_t)BCN*NSEQ*DM];     // [z][n][d]
__device__ __half g_kp [(size_t)BCN*NSEQ*DM];     // [z][m][d]
__device__ __half g_vp [(size_t)BCN*NSEQ*DM];     // [z][m][d]
__device__ __half g_ctx[(size_t)BCN*NSEQ*DM];     // [z][n][d]
__device__ __half g_sc [(size_t)BCN*NSEQ*NSEQ];   // fp16 scores / normalized attn
__device__ __half g_wt [4*(size_t)DM*DM];         // W^T as [out][in], fp16

// ---------------------------------------------------------------------------
__device__ __forceinline__ uint32_t smem_u32(const void* p) {
    uint32_t a;
    asm("{ .reg .u64 t; cvta.to.shared.u64 t, %1; cvt.u32.u64 %0, t; }"
        : "=r"(a) : "l"(p));
    return a;
}
__device__ __forceinline__ void cpa16(uint32_t d, const void* s) {
    asm volatile("cp.async.cg.shared.global [%0], [%1], 16;" :: "r"(d), "l"(s));
}
__device__ __forceinline__ void cpcommit() {
    asm volatile("cp.async.commit_group;" ::: "memory");
}
template<int N> __device__ __forceinline__ void cpwait() {
    asm volatile("cp.async.wait_group %0;" :: "n"(N) : "memory");
}
#define LDSM4(r, a)                                                           \
    asm volatile("ldmatrix.sync.aligned.m8n8.x4.shared.b16 {%0,%1,%2,%3}, [%4];" \
        : "=r"((r)[0]), "=r"((r)[1]), "=r"((r)[2]), "=r"((r)[3]) : "r"(a))
#define LDSM4T(r, a)                                                          \
    asm volatile("ldmatrix.sync.aligned.m8n8.x4.trans.shared.b16 {%0,%1,%2,%3}, [%4];" \
        : "=r"((r)[0]), "=r"((r)[1]), "=r"((r)[2]), "=r"((r)[3]) : "r"(a))

__device__ __forceinline__ void mma16816(float* c, const uint32_t* a,
                                         uint32_t b0, uint32_t b1) {
    asm volatile(
        "mma.sync.aligned.m16n8k16.row.col.f32.f16.f16.f32 "
        "{%0,%1,%2,%3}, {%4,%5,%6,%7}, {%8,%9}, {%0,%1,%2,%3};"
        : "+f"(c[0]), "+f"(c[1]), "+f"(c[2]), "+f"(c[3])
        : "r"(a[0]), "r"(a[1]), "r"(a[2]), "r"(a[3]), "r"(b0), "r"(b1));
}

// ---------------------------------------------------------------------------
// Block tile 128x256xKC(=64), 8 warps of 64x64, 3-stage cp.async pipeline.
// MODE 0: projection  C = A(f32)@W^T + b,  remap (b,n,c)->(b,c,n), half out
// MODE 2: scores      C = scale * Q @ K^T, half in, HALF out (to g_sc)
// MODE 3: AV          C = attnH @ V, A half, V loaded [m][d] w/ ldmatrix.trans
// MODE 4: out proj    C = relu(ctx(h)@Wo^T + b), remap (b,c,n)->(b,n,c), f32
// ---------------------------------------------------------------------------
#define KC     64
#define LDA_S  72          // halves: 64 + 8 pad
#define LDB_T  264         // halves for BTR tiles (256 + 8 pad)
#define ABUF   (128*LDA_S)             // 9216 halves
#define BBUF   (256*LDA_S)             // 18432 halves (>= 64*LDB_T = 16896)
#define STAGE  (ABUF + BBUF)
#define NSTG   3

template<int MODE>
__global__ __launch_bounds__(256) void gemm_mma(
    const void* __restrict__ Ag, const __half* __restrict__ Bg,
    const float* __restrict__ bias, void* __restrict__ Cg)
{
    extern __shared__ __half sh[];
    constexpr int  K     = (MODE == 3) ? NSEQ : DM;
    constexpr int  ITERS = K / KC;
    constexpr bool ACVT  = (MODE == 0);
    constexpr bool BTR   = (MODE == 3);
    constexpr int  LDAE  = (MODE == 3) ? NSEQ : DM;

    const int tid = threadIdx.x, lane = tid & 31, wid = tid >> 5;
    const int wr = wid >> 2, wc = wid & 3;
    const int z = blockIdx.z;
    const int rowBase = blockIdx.y * 128, colBase = blockIdx.x * 256;

    const float*  Af = (const float*)Ag;
    const __half* Ah = (const __half*)Ag +
        (MODE == 2 ? (size_t)z*NSEQ*DM : MODE == 3 ? (size_t)z*NSEQ*NSEQ : 0);
    const __half* Bp = Bg + ((MODE == 2 || MODE == 3) ? (size_t)z*NSEQ*DM : 0);

    const uint32_t sbase = smem_u32(sh);

    float acc[4][8][4];
    #pragma unroll
    for (int i = 0; i < 4; i++)
        #pragma unroll
        for (int j = 0; j < 8; j++)
            #pragma unroll
            for (int q = 0; q < 4; q++) acc[i][j][q] = 0.f;

    // ---- loaders ----
    const int avr = tid & 127;      // CVT: row
    const int avh = tid >> 7;       // CVT: 32-col half (0/1)
    float4 fA[8];

    auto loadA_cvt = [&](int kb) {
        const float* s = Af + (size_t)(rowBase + avr) * LDAE + kb + avh * 32;
        #pragma unroll
        for (int u = 0; u < 8; u++) fA[u] = *(const float4*)(s + u*4);
    };
    auto stsA_cvt = [&](int buf) {
        __half hv[32];
        #pragma unroll
        for (int u = 0; u < 8; u++) {
            hv[u*4+0] = __float2half_rn(fA[u].x);
            hv[u*4+1] = __float2half_rn(fA[u].y);
            hv[u*4+2] = __float2half_rn(fA[u].z);
            hv[u*4+3] = __float2half_rn(fA[u].w);
        }
        __half* d = sh + buf*STAGE + avr*LDA_S + avh*32;
        #pragma unroll
        for (int u = 0; u < 4; u++)
            *((uint4*)d + u) = ((uint4*)hv)[u];
    };
    auto issueA_async = [&](int buf, int kb) {
        #pragma unroll
        for (int i = 0; i < 4; i++) {
            int idx = tid + i*256;
            int h = idx & 7, r = idx >> 3;
            cpa16(sbase + (uint32_t)(buf*STAGE + r*LDA_S + h*8)*2,
                  Ah + (size_t)(rowBase + r)*LDAE + kb + h*8);
        }
    };
    auto issueB = [&](int buf, int kb) {
        if constexpr (BTR) {
            #pragma unroll
            for (int i = 0; i < 8; i++) {
                int idx = tid + i*256;
                int r = idx >> 5, h = idx & 31;
                cpa16(sbase + (uint32_t)(buf*STAGE + ABUF + r*LDB_T + h*8)*2,
                      Bp + (size_t)(kb + r)*DM + colBase + h*8);
            }
        } else {
            #pragma unroll
            for (int i = 0; i < 8; i++) {
                int idx = tid + i*256;
                int h = idx & 7, r = idx >> 3;
                cpa16(sbase + (uint32_t)(buf*STAGE + ABUF + r*LDA_S + h*8)*2,
                      Bp + (size_t)(colBase + r)*DM + kb + h*8);
            }
        }
    };

    // ---- prologue: stage 0 and 1 ----
    if constexpr (ACVT) {
        loadA_cvt(0);  stsA_cvt(0);
        loadA_cvt(KC); stsA_cvt(1);
        issueB(0, 0);  cpcommit();
        issueB(1, KC); cpcommit();
    } else {
        issueA_async(0, 0);  issueB(0, 0);  cpcommit();
        issueA_async(1, KC); issueB(1, KC); cpcommit();
    }

    // ---- main loop: single __syncthreads per iteration ----
    for (int it = 0; it < ITERS; ++it) {
        const int cur = it % NSTG;
        if (it + 1 < ITERS) cpwait<1>(); else cpwait<0>();
        __syncthreads();

        const bool pf = (it + 2 < ITERS);
        const int  nb = (it + 2) % NSTG, kb = (it + 2) * KC;
        if (pf) {
            if constexpr (ACVT) { loadA_cvt(kb); issueB(nb, kb); cpcommit(); }
            else { issueA_async(nb, kb); issueB(nb, kb); cpcommit(); }
        }

        #pragma unroll
        for (int ks = 0; ks < KC/16; ks++) {
            uint32_t a[4][4], b[4][4];
            #pragma unroll
            for (int i = 0; i < 4; i++) {
                int row = wr*64 + i*16 + (lane & 15);
                int col = ks*16 + ((lane >> 4) << 3);
                LDSM4(a[i], sbase + (uint32_t)(cur*STAGE + row*LDA_S + col)*2);
            }
            #pragma unroll
            for (int t = 0; t < 4; t++) {
                if constexpr (BTR) {
                    int row = ks*16 + (lane & 7) + (((lane >> 3) & 1) << 3);
                    int col = wc*64 + t*16 + ((lane >> 4) << 3);
                    LDSM4T(b[t], sbase + (uint32_t)(cur*STAGE + ABUF + row*LDB_T + col)*2);
                } else {
                    int row = wc*64 + t*16 + (lane & 7) + ((lane >> 4) << 3);
                    int col = ks*16 + (((lane >> 3) & 1) << 3);
                    LDSM4(b[t], sbase + (uint32_t)(cur*STAGE + ABUF + row*LDA_S + col)*2);
                }
            }
            #pragma unroll
            for (int i = 0; i < 4; i++)
                #pragma unroll
                for (int t = 0; t < 4; t++) {
                    mma16816(acc[i][2*t],   a[i], b[t][0], b[t][1]);
                    mma16816(acc[i][2*t+1], a[i], b[t][2], b[t][3]);
                }
        }
        if (pf) {
            if constexpr (ACVT) stsA_cvt(nb);   // into stage it+2 (safe: sync passed)
        }
    }

    // ---- epilogue: direct from mma accumulators ----
    const int g = lane >> 2, tig = lane & 3;
    float bb0[8], bb1[8];
    if constexpr (MODE == 0 || MODE == 4) {
        #pragma unroll
        for (int j = 0; j < 8; j++) {
            int gc = colBase + wc*64 + j*8 + tig*2;
            bb0[j] = __ldg(&bias[gc]);
            bb1[j] = __ldg(&bias[gc + 1]);
        }
    }
    const float scale = 0.04419417382415922f;   // 1/sqrt(512)

    #pragma unroll
    for (int i = 0; i < 4; i++) {
        int r0 = rowBase + wr*64 + i*16 + g;
        #pragma unroll
        for (int rr = 0; rr < 2; rr++) {
            int gr = r0 + rr*8;
            #pragma unroll
            for (int j = 0; j < 8; j++) {
                float c0 = acc[i][j][rr*2 + 0], c1 = acc[i][j][rr*2 + 1];
                int gc = colBase + wc*64 + j*8 + tig*2;
                if constexpr (MODE == 0) {
                    int b = gr >> 14, n = (gr >> 3) & 2047, ch = gr & 7;
                    int zz = (b << 3) | ch;
                    *(__half2*)((__half*)Cg + ((size_t)zz*NSEQ + n)*DM + gc) =
                        __floats2half2_rn(c0 + bb0[j], c1 + bb1[j]);
                } else if constexpr (MODE == 2) {
                    *(__half2*)((__half*)Cg + ((size_t)z*NSEQ + gr)*NSEQ + gc) =
                        __floats2half2_rn(c0 * scale, c1 * scale);
                } else if constexpr (MODE == 3) {
                    *(__half2*)((__half*)Cg + ((size_t)z*NSEQ + gr)*DM + gc) =
                        __floats2half2_rn(c0, c1);
                } else {  // MODE 4
                    int b = gr >> 14, ch = (gr >> 11) & 7, n = gr & 2047;
                    int rm = (b << 14) | (n << 3) | ch;
                    float2 o;
                    o.x = fmaxf(c0 + bb0[j], 0.f);
                    o.y = fmaxf(c1 + bb1[j], 0.f);
                    *(float2*)((float*)Cg + (size_t)rm*DM + gc) = o;
                }
            }
        }
    }
}

// ---------------------------------------------------------------------------
// W transpose + fp16 convert: W[in][out] f32 -> Wt[out][in] half
// ---------------------------------------------------------------------------
__global__ __launch_bounds__(256) void prep_w_kernel(
    const float* __restrict__ W, __half* __restrict__ Wt)
{
    __shared__ float t[32][33];
    const int bx = blockIdx.x * 32;   // out
    const int by = blockIdx.y * 32;   // in
    const int tx = threadIdx.x & 31;
    const int ty = threadIdx.x >> 5;  // 0..7
    #pragma unroll
    for (int i = 0; i < 4; i++) {
        int r = ty * 4 + i;
        t[r][tx] = W[(size_t)(by + r) * DM + bx + tx];
    }
    __syncthreads();
    #pragma unroll
    for (int i = 0; i < 4; i++) {
        int r = ty * 4 + i;   // out-local
        Wt[(size_t)(bx + r) * DM + by + tx] = __float2half_rn(t[tx][r]);
    }
}

// ---------------------------------------------------------------------------
// Softmax: warp per row. Reads fp16 scores from Sh, writes fp32 attn to Af
// and normalized fp16 back to Sh (in place) for the AV GEMM.
// ---------------------------------------------------------------------------
__global__ __launch_bounds__(256) void softmax_kernel(
    __half* __restrict__ Sh, float* __restrict__ Af)
{
    const int row  = blockIdx.x * 8 + (threadIdx.x >> 5);
    const int lane = threadIdx.x & 31;
    __half* p = Sh + (size_t)row * NSEQ;
    float*  o = Af + (size_t)row * NSEQ;

    uint2 hv[16];
    #pragma unroll
    for (int j = 0; j < 16; j++)
        hv[j] = *(const uint2*)(p + lane*4 + j*128);

    float v[64];
    #pragma unroll
    for (int j = 0; j < 16; j++) {
        float2 a = __half22float2(*(__half2*)&hv[j].x);
        float2 b = __half22float2(*(__half2*)&hv[j].y);
        v[4*j+0] = a.x; v[4*j+1] = a.y; v[4*j+2] = b.x; v[4*j+3] = b.y;
    }

    float mx = v[0];
    #pragma unroll
    for (int i = 1; i < 64; i++) mx = fmaxf(mx, v[i]);
    #pragma unroll
    for (int s = 16; s > 0; s >>= 1)
        mx = fmaxf(mx, __shfl_xor_sync(0xffffffffu, mx, s));

    float sum = 0.f;
    #pragma unroll
    for (int i = 0; i < 64; i++) { v[i] = expf(v[i] - mx); sum += v[i]; }
    #pragma unroll
    for (int s = 16; s > 0; s >>= 1)
        sum += __shfl_xor_sync(0xffffffffu, sum, s);
    const float inv = 1.f / sum;

    #pragma unroll
    for (int j = 0; j < 16; j++) {
        float4 f;
        f.x = v[4*j+0] * inv; f.y = v[4*j+1] * inv;
        f.z = v[4*j+2] * inv; f.w = v[4*j+3] * inv;
        *(float4*)(o + lane*4 + j*128) = f;
        __half2 h0 = __floats2half2_rn(f.x, f.y);
        __half2 h1 = __floats2half2_rn(f.z, f.w);
        uint2 u; u.x = *(uint32_t*)&h0; u.y = *(uint32_t*)&h1;
        *(uint2*)(p + lane*4 + j*128) = u;
    }
}

// ---------------------------------------------------------------------------
#define SMEM_BYTES (NSTG * STAGE * 2)   // 165888

extern "C" void kernel_launch(void* const* d_in, const int* in_sizes, int n_in,
                              void* d_out, int out_size)
{
    const float* q  = (const float*)d_in[0];
    const float* k  = (const float*)d_in[1];
    const float* v  = (const float*)d_in[2];
    const float* Wq = (const float*)d_in[3];
    const float* bq = (const float*)d_in[4];
    const float* Wk = (const float*)d_in[5];
    const float* bk = (const float*)d_in[6];
    const float* Wv = (const float*)d_in[7];
    const float* bv = (const float*)d_in[8];
    const float* Wo = (const float*)d_in[9];
    const float* bo = (const float*)d_in[10];

    float* out  = (float*)d_out;               // [b,n,c,d]
    float* attn = out + OUT_OFF_ATTN;          // [b,c,n,m]

    void *pq, *pk, *pv, *pc, *ps, *pw;
    cudaGetSymbolAddress(&pq, g_qp);
    cudaGetSymbolAddress(&pk, g_kp);
    cudaGetSymbolAddress(&pv, g_vp);
    cudaGetSymbolAddress(&pc, g_ctx);
    cudaGetSymbolAddress(&ps, g_sc);
    cudaGetSymbolAddress(&pw, g_wt);
    __half* qp  = (__half*)pq;
    __half* kp  = (__half*)pk;
    __half* vp  = (__half*)pv;
    __half* ctx = (__half*)pc;
    __half* sc  = (__half*)ps;
    __half* wt  = (__half*)pw;

    cudaFuncSetAttribute(gemm_mma<0>, cudaFuncAttributeMaxDynamicSharedMemorySize, SMEM_BYTES);
    cudaFuncSetAttribute(gemm_mma<2>, cudaFuncAttributeMaxDynamicSharedMemorySize, SMEM_BYTES);
    cudaFuncSetAttribute(gemm_mma<3>, cudaFuncAttributeMaxDynamicSharedMemorySize, SMEM_BYTES);
    cudaFuncSetAttribute(gemm_mma<4>, cudaFuncAttributeMaxDynamicSharedMemorySize, SMEM_BYTES);

    // transpose + convert weights
    dim3 gW(16, 16);
    prep_w_kernel<<<gW, 256>>>(Wq, wt + 0 * (size_t)DM * DM);
    prep_w_kernel<<<gW, 256>>>(Wk, wt + 1 * (size_t)DM * DM);
    prep_w_kernel<<<gW, 256>>>(Wv, wt + 2 * (size_t)DM * DM);
    prep_w_kernel<<<gW, 256>>>(Wo, wt + 3 * (size_t)DM * DM);

    // projections: M=65536, N=512
    dim3 gP(DM / 256, MROWS / 128, 1);           // (2, 512)
    gemm_mma<0><<<gP, 256, SMEM_BYTES>>>(q, wt + 0 * (size_t)DM * DM, bq, qp);
    gemm_mma<0><<<gP, 256, SMEM_BYTES>>>(k, wt + 1 * (size_t)DM * DM, bk, kp);
    gemm_mma<0><<<gP, 256, SMEM_BYTES>>>(v, wt + 2 * (size_t)DM * DM, bv, vp);

    // scores: per z, M=N=2048, K=512, fp16 out to g_sc
    dim3 gS(NSEQ / 256, NSEQ / 128, BCN);        // (8, 16, 32)
    gemm_mma<2><<<gS, 256, SMEM_BYTES>>>(qp, kp, nullptr, sc);

    // softmax: fp16 in -> fp32 attn + fp16 normalized (in place)
    softmax_kernel<<<BCN * NSEQ / 8, 256>>>(sc, attn);

    // AV: per z, M=2048, N=512, K=2048, A = fp16 normalized attn
    dim3 gA(DM / 256, NSEQ / 128, BCN);          // (2, 16, 32)
    gemm_mma<3><<<gA, 256, SMEM_BYTES>>>(sc, vp, nullptr, ctx);

    // out projection
    gemm_mma<4><<<gP, 256, SMEM_BYTES>>>(ctx, wt + 3 * (size_t)DM * DM, bo, out);
}